// round 1
// baseline (speedup 1.0000x reference)
#include <cuda_runtime.h>

// C = tril( tril(A) @ tril(B) ), N=4096, fp32.
// Block (bi,bj) computes 128x128 tile. Only k-tiles in [bj*128, (bi+1)*128)
// contribute (triangular operands), giving ~N^3/6 MACs total.

#define NDIM 4096
#define BM 128
#define BN 128
#define BK 16
#define TM 8
#define TN 8

__global__ __launch_bounds__(256, 2)
void trilmm_kernel(const float* __restrict__ A,
                   const float* __restrict__ B,
                   float* __restrict__ C) {
    const int bi = blockIdx.y;   // row tile
    const int bj = blockIdx.x;   // col tile
    const int rowBase = bi * BM;
    const int colBase = bj * BN;

    __shared__ float As[BK][BM];   // transposed: As[k][m]
    __shared__ float Bs[BK][BN];   // Bs[k][n]

    const int tid = threadIdx.x;
    const int tx = tid & 15;       // 0..15 -> col group
    const int ty = tid >> 4;       // 0..15 -> row group

    float acc[TM][TN];
#pragma unroll
    for (int i = 0; i < TM; i++)
#pragma unroll
        for (int j = 0; j < TN; j++) acc[i][j] = 0.0f;

    // A loader mapping: 128 rows x 16 k = 2048 floats = 512 float4, 2 per thread
    const int aRow0 = tid >> 2;          // 0..63
    const int aCol  = (tid & 3) * 4;     // k offset 0,4,8,12
    // B loader mapping: 16 k x 128 cols = 512 float4, 2 per thread
    const int bRow0 = tid >> 5;          // 0..7
    const int bCol  = (tid & 31) * 4;    // col offset

    const int kStart = colBase;                              // first k that can contribute
    const int kEnd   = (bi >= bj) ? (rowBase + BM) : kStart; // upper blocks: no work

    for (int k0 = kStart; k0 < kEnd; k0 += BK) {
        // ---- load A tile (mask: tril(A) => keep k <= row) ----
#pragma unroll
        for (int r = 0; r < 2; r++) {
            const int row = rowBase + aRow0 + r * 64;
            const int k   = k0 + aCol;
            float4 v = *reinterpret_cast<const float4*>(
                &A[(size_t)row * NDIM + k]);
            As[aCol + 0][aRow0 + r * 64] = (k + 0 <= row) ? v.x : 0.0f;
            As[aCol + 1][aRow0 + r * 64] = (k + 1 <= row) ? v.y : 0.0f;
            As[aCol + 2][aRow0 + r * 64] = (k + 2 <= row) ? v.z : 0.0f;
            As[aCol + 3][aRow0 + r * 64] = (k + 3 <= row) ? v.w : 0.0f;
        }
        // ---- load B tile (mask: tril(B) => keep k >= col) ----
#pragma unroll
        for (int r = 0; r < 2; r++) {
            const int k   = k0 + bRow0 + r * 8;
            const int col = colBase + bCol;
            float4 v = *reinterpret_cast<const float4*>(
                &B[(size_t)k * NDIM + col]);
            if (k < col + 0) v.x = 0.0f;
            if (k < col + 1) v.y = 0.0f;
            if (k < col + 2) v.z = 0.0f;
            if (k < col + 3) v.w = 0.0f;
            *reinterpret_cast<float4*>(&Bs[bRow0 + r * 8][bCol]) = v;
        }
        __syncthreads();

        // ---- compute ----
#pragma unroll
        for (int kk = 0; kk < BK; kk++) {
            float ra[TM], rb[TN];
#pragma unroll
            for (int i = 0; i < TM; i++) ra[i] = As[kk][ty * TM + i];
#pragma unroll
            for (int j = 0; j < TN; j++) rb[j] = Bs[kk][tx * TN + j];
#pragma unroll
            for (int i = 0; i < TM; i++)
#pragma unroll
                for (int j = 0; j < TN; j++)
                    acc[i][j] = fmaf(ra[i], rb[j], acc[i][j]);
        }
        __syncthreads();
    }

    // ---- epilogue: write with tril mask (output poisoned -> must write zeros too) ----
#pragma unroll
    for (int i = 0; i < TM; i++) {
        const int row = rowBase + ty * TM + i;
#pragma unroll
        for (int j4 = 0; j4 < TN; j4 += 4) {
            const int col = colBase + tx * TN + j4;
            float4 v;
            v.x = (row >= col + 0) ? acc[i][j4 + 0] : 0.0f;
            v.y = (row >= col + 1) ? acc[i][j4 + 1] : 0.0f;
            v.z = (row >= col + 2) ? acc[i][j4 + 2] : 0.0f;
            v.w = (row >= col + 3) ? acc[i][j4 + 3] : 0.0f;
            *reinterpret_cast<float4*>(&C[(size_t)row * NDIM + col]) = v;
        }
    }
}

extern "C" void kernel_launch(void* const* d_in, const int* in_sizes, int n_in,
                              void* d_out, int out_size) {
    const float* A = (const float*)d_in[0];
    const float* B = (const float*)d_in[1];
    float* C = (float*)d_out;

    dim3 grid(NDIM / BN, NDIM / BM);  // (bj, bi) = 32 x 32
    dim3 block(256);
    trilmm_kernel<<<grid, block>>>(A, B, C);
}

// round 3
// speedup vs baseline: 3.2171x; 3.2171x over previous
#include <cuda_runtime.h>
#include <cuda_bf16.h>
#include <cstdint>

#define N4K 4096

// ---------------- device scratch (allocation-free) ----------------
__device__ __nv_bfloat16 g_Ahi[(size_t)N4K * N4K];
__device__ __nv_bfloat16 g_Alo[(size_t)N4K * N4K];
__device__ __nv_bfloat16 g_Bhi[(size_t)N4K * N4K];   // transposed: [N, K]
__device__ __nv_bfloat16 g_Blo[(size_t)N4K * N4K];   // transposed: [N, K]

// ---------------- helpers ----------------
__device__ __forceinline__ uint32_t smem_u32(const void* p) {
    uint32_t a;
    asm("{ .reg .u64 t; cvta.to.shared.u64 t, %1; cvt.u32.u64 %0, t; }"
        : "=r"(a) : "l"(p));
    return a;
}

__device__ __forceinline__ void ldsm4(uint32_t* r, uint32_t addr) {
    asm volatile("ldmatrix.sync.aligned.m8n8.x4.shared.b16 {%0,%1,%2,%3}, [%4];"
        : "=r"(r[0]), "=r"(r[1]), "=r"(r[2]), "=r"(r[3]) : "r"(addr));
}

__device__ __forceinline__ void mma16816(float* c, const uint32_t* a,
                                         uint32_t b0, uint32_t b1) {
    asm volatile(
        "mma.sync.aligned.m16n8k16.row.col.f32.bf16.bf16.f32 "
        "{%0,%1,%2,%3},{%4,%5,%6,%7},{%8,%9},{%0,%1,%2,%3};"
        : "+f"(c[0]), "+f"(c[1]), "+f"(c[2]), "+f"(c[3])
        : "r"(a[0]), "r"(a[1]), "r"(a[2]), "r"(a[3]), "r"(b0), "r"(b1));
}

__device__ __forceinline__ void cpasync16(uint32_t saddr, const void* g) {
    asm volatile("cp.async.cg.shared.global [%0], [%1], 16;"
        :: "r"(saddr), "l"(g));
}

// ---------------- conversion kernels ----------------
__global__ void __launch_bounds__(256) conv_a(const float* __restrict__ A) {
    size_t t = (size_t)blockIdx.x * 256 + threadIdx.x;   // float4 index
    int i  = (int)(t >> 10);          // row
    int c4 = (int)(t & 1023) << 2;    // col start
    float4 v = *reinterpret_cast<const float4*>(A + (size_t)i * N4K + c4);
    float a0 = (c4 + 0 <= i) ? v.x : 0.0f;
    float a1 = (c4 + 1 <= i) ? v.y : 0.0f;
    float a2 = (c4 + 2 <= i) ? v.z : 0.0f;
    float a3 = (c4 + 3 <= i) ? v.w : 0.0f;
    __nv_bfloat16 h0 = __float2bfloat16(a0), h1 = __float2bfloat16(a1);
    __nv_bfloat16 h2 = __float2bfloat16(a2), h3 = __float2bfloat16(a3);
    __nv_bfloat16 l0 = __float2bfloat16(a0 - __bfloat162float(h0));
    __nv_bfloat16 l1 = __float2bfloat16(a1 - __bfloat162float(h1));
    __nv_bfloat16 l2 = __float2bfloat16(a2 - __bfloat162float(h2));
    __nv_bfloat16 l3 = __float2bfloat16(a3 - __bfloat162float(h3));
    uint2 uh, ul;
    uh.x = (uint32_t)__bfloat16_as_ushort(h0) | ((uint32_t)__bfloat16_as_ushort(h1) << 16);
    uh.y = (uint32_t)__bfloat16_as_ushort(h2) | ((uint32_t)__bfloat16_as_ushort(h3) << 16);
    ul.x = (uint32_t)__bfloat16_as_ushort(l0) | ((uint32_t)__bfloat16_as_ushort(l1) << 16);
    ul.y = (uint32_t)__bfloat16_as_ushort(l2) | ((uint32_t)__bfloat16_as_ushort(l3) << 16);
    *reinterpret_cast<uint2*>(&g_Ahi[(size_t)i * N4K + c4]) = uh;
    *reinterpret_cast<uint2*>(&g_Alo[(size_t)i * N4K + c4]) = ul;
}

// B: transpose + mask(tril: keep k >= j) -> Bt[j][k]
__global__ void __launch_bounds__(256) conv_b(const float* __restrict__ B) {
    __shared__ float tile[32][33];
    int j0 = blockIdx.x * 32, k0 = blockIdx.y * 32;
    int tx = threadIdx.x & 31, ty = threadIdx.x >> 5;   // ty 0..7
#pragma unroll
    for (int yy = 0; yy < 4; yy++) {
        int k = k0 + ty + yy * 8;
        int j = j0 + tx;
        float v = B[(size_t)k * N4K + j];
        if (k < j) v = 0.0f;
        tile[ty + yy * 8][tx] = v;
    }
    __syncthreads();
#pragma unroll
    for (int yy = 0; yy < 4; yy++) {
        int j = j0 + ty + yy * 8;
        int k = k0 + tx;
        float v = tile[tx][ty + yy * 8];
        __nv_bfloat16 hi = __float2bfloat16(v);
        __nv_bfloat16 lo = __float2bfloat16(v - __bfloat162float(hi));
        g_Bhi[(size_t)j * N4K + k] = hi;
        g_Blo[(size_t)j * N4K + k] = lo;
    }
}

// ---------------- zero upper triangle tiles ----------------
__global__ void __launch_bounds__(256) zero_upper(float* __restrict__ C) {
    int bj = blockIdx.x, bi = blockIdx.y;
    if (bi >= bj) return;
    int rowBase = bi * 128, colBase = bj * 128;
    float4 z = make_float4(0.f, 0.f, 0.f, 0.f);
#pragma unroll
    for (int it = 0; it < 16; it++) {
        int idx = threadIdx.x + it * 256;       // float4 index in 128x32
        int r = idx >> 5, c4 = (idx & 31) << 2;
        *reinterpret_cast<float4*>(&C[(size_t)(rowBase + r) * N4K + colBase + c4]) = z;
    }
}

// ---------------- main warp-MMA GEMM ----------------
// SMEM: padded rows, 32 bf16 data + 8 pad = 40 halves = 80 bytes / row
#define STRIDE_B 80
#define TILE_B   (128 * STRIDE_B)       // 10240
#define STAGE_B  (4 * TILE_B)           // 40960
#define SMEM_SZ  (2 * STAGE_B)          // 81920

__device__ __forceinline__ void load_stage(uint32_t sbase, int stage, int k0,
                                           int rowBase, int colBase, int tid) {
    const int row = tid >> 2;           // 0..63
    const int ch  = tid & 3;            // 16B chunk (8 halves)
    const __nv_bfloat16* srcs[4] = {
        g_Ahi + (size_t)rowBase * N4K,
        g_Alo + (size_t)rowBase * N4K,
        g_Bhi + (size_t)colBase * N4K,
        g_Blo + (size_t)colBase * N4K };
    const uint32_t sb = sbase + stage * STAGE_B;
#pragma unroll
    for (int t = 0; t < 4; t++) {
        const __nv_bfloat16* src = srcs[t];
#pragma unroll
        for (int r = 0; r < 2; r++) {
            int rr = row + r * 64;
            cpasync16(sb + t * TILE_B + rr * STRIDE_B + ch * 16,
                      src + (size_t)rr * N4K + k0 + ch * 8);
        }
    }
    asm volatile("cp.async.commit_group;" ::: "memory");
}

__global__ void __launch_bounds__(256, 1)
trilmm_mma(float* __restrict__ C) {
    extern __shared__ char smem[];
    const uint32_t sbase = smem_u32(smem);
    const int tid  = threadIdx.x;
    const int wid  = tid >> 5;
    const int lane = tid & 31;
    const int wr = wid >> 2;            // 0..1  -> m offset wr*64
    const int wc = wid & 3;             // 0..3  -> n offset wc*32

    // diagonal-major block mapping (largest work first)
    int rem = blockIdx.x, cnt = 1, d = 31;
    while (rem >= cnt) { rem -= cnt; d--; cnt++; }
    const int bj = rem, bi = bj + d;
    const int rowBase = bi * 128, colBase = bj * 128;
    const int nStages = (d + 1) * 4;    // K chunks of 32

    float acc[4][4][4];
#pragma unroll
    for (int i = 0; i < 4; i++)
#pragma unroll
        for (int j = 0; j < 4; j++)
#pragma unroll
            for (int k = 0; k < 4; k++) acc[i][j][k] = 0.0f;

    // per-thread ldmatrix byte offsets within a tile
    const uint32_t aOff = (uint32_t)((wr * 64 + (lane & 15)) * STRIDE_B
                                     + ((lane >> 4) * 8) * 2);
    const uint32_t bOff = (uint32_t)((wc * 32 + ((lane >> 4) & 1) * 8 + (lane & 7)) * STRIDE_B
                                     + (lane & 8) * 2);

    load_stage(sbase, 0, colBase, rowBase, colBase, tid);

    for (int s = 0; s < nStages; s++) {
        const bool pf = (s + 1 < nStages);
        if (pf) load_stage(sbase, (s + 1) & 1, colBase + (s + 1) * 32,
                           rowBase, colBase, tid);
        if (pf) asm volatile("cp.async.wait_group 1;" ::: "memory");
        else    asm volatile("cp.async.wait_group 0;" ::: "memory");
        __syncthreads();

        const uint32_t sb  = sbase + (s & 1) * STAGE_B;
        const uint32_t bAh = sb + 0 * TILE_B + aOff;
        const uint32_t bAl = sb + 1 * TILE_B + aOff;
        const uint32_t bBh = sb + 2 * TILE_B + bOff;
        const uint32_t bBl = sb + 3 * TILE_B + bOff;

#pragma unroll
        for (int ks = 0; ks < 2; ks++) {
            const uint32_t ko = ks * 32;   // 16 halves = 32 bytes
            uint32_t ah[4][4], al[4][4], bh[2][4], bl[2][4];
#pragma unroll
            for (int mf = 0; mf < 4; mf++)
                ldsm4(ah[mf], bAh + mf * 16 * STRIDE_B + ko);
#pragma unroll
            for (int ng = 0; ng < 2; ng++)
                ldsm4(bh[ng], bBh + ng * 16 * STRIDE_B + ko);
            // hi * hi
#pragma unroll
            for (int mf = 0; mf < 4; mf++)
#pragma unroll
                for (int nf = 0; nf < 4; nf++)
                    mma16816(acc[mf][nf], ah[mf],
                             bh[nf >> 1][(nf & 1) * 2], bh[nf >> 1][(nf & 1) * 2 + 1]);
            // hi * lo
#pragma unroll
            for (int ng = 0; ng < 2; ng++)
                ldsm4(bl[ng], bBl + ng * 16 * STRIDE_B + ko);
#pragma unroll
            for (int mf = 0; mf < 4; mf++)
#pragma unroll
                for (int nf = 0; nf < 4; nf++)
                    mma16816(acc[mf][nf], ah[mf],
                             bl[nf >> 1][(nf & 1) * 2], bl[nf >> 1][(nf & 1) * 2 + 1]);
            // lo * hi
#pragma unroll
            for (int mf = 0; mf < 4; mf++)
                ldsm4(al[mf], bAl + mf * 16 * STRIDE_B + ko);
#pragma unroll
            for (int mf = 0; mf < 4; mf++)
#pragma unroll
                for (int nf = 0; nf < 4; nf++)
                    mma16816(acc[mf][nf], al[mf],
                             bh[nf >> 1][(nf & 1) * 2], bh[nf >> 1][(nf & 1) * 2 + 1]);
        }
        __syncthreads();
    }

    // ---- epilogue: tril mask + store ----
#pragma unroll
    for (int mf = 0; mf < 4; mf++) {
        const int r0 = rowBase + wr * 64 + mf * 16 + (lane >> 2);
        const int r1 = r0 + 8;
#pragma unroll
        for (int nf = 0; nf < 4; nf++) {
            const int c0 = colBase + wc * 32 + nf * 8 + (lane & 3) * 2;
            const float* a4 = acc[mf][nf];
            C[(size_t)r0 * N4K + c0 + 0] = (r0 >= c0 + 0) ? a4[0] : 0.0f;
            C[(size_t)r0 * N4K + c0 + 1] = (r0 >= c0 + 1) ? a4[1] : 0.0f;
            C[(size_t)r1 * N4K + c0 + 0] = (r1 >= c0 + 0) ? a4[2] : 0.0f;
            C[(size_t)r1 * N4K + c0 + 1] = (r1 >= c0 + 1) ? a4[3] : 0.0f;
        }
    }
}

// ---------------- launch ----------------
extern "C" void kernel_launch(void* const* d_in, const int* in_sizes, int n_in,
                              void* d_out, int out_size) {
    const float* A = (const float*)d_in[0];
    const float* B = (const float*)d_in[1];
    float* C = (float*)d_out;

    static int attrSet = 0;
    if (!attrSet) {
        cudaFuncSetAttribute(trilmm_mma,
                             cudaFuncAttributeMaxDynamicSharedMemorySize, SMEM_SZ);
        attrSet = 1;
    }

    conv_a<<<16384, 256>>>(A);
    conv_b<<<dim3(128, 128), 256>>>(B);
    zero_upper<<<dim3(32, 32), 256>>>(C);
    trilmm_mma<<<528, 256, SMEM_SZ>>>(C);
}